// round 2
// baseline (speedup 1.0000x reference)
#include <cuda_runtime.h>

#define NR 6144
typedef unsigned long long ull;

// ------------------------- scratch (device globals) -------------------------
__device__ float g_fe [2][NR*64];
__device__ float g_cs [2][64];
__device__ float g_x  [2][NR*64];
__device__ float g_q  [2][NR*64];
__device__ float g_k  [2][NR*64];
__device__ float g_v  [2][NR*64];
__device__ float g_kvp[2][48][512];
__device__ float g_M  [2][4096];
__device__ float g_emb[2][NR*64];
__device__ float g_comb[NR*64];
__device__ float g_u  [2][NR*64];

// ------------------------- helpers -------------------------
__device__ __forceinline__ float spikef(float x){
    float y = 4.0f * x;
    y = fminf(fmaxf(y, 0.0f), 4.0f);
    return floorf(y + 0.5f) * 0.25f;
}
__device__ __forceinline__ ull pack2(float lo, float hi){
    ull r;
    asm("mov.b64 %0, {%1, %2};" : "=l"(r) : "r"(__float_as_uint(lo)), "r"(__float_as_uint(hi)));
    return r;
}
__device__ __forceinline__ ull dup2(float x){ return pack2(x, x); }
__device__ __forceinline__ void ffma2(ull &d, ull a, ull b){
    asm("fma.rn.f32x2 %0, %1, %2, %0;" : "+l"(d) : "l"(a), "l"(b));
}
__device__ __forceinline__ void unpack2(ull v, float &lo, float &hi){
    unsigned a, b;
    asm("mov.b64 {%0, %1}, %2;" : "=r"(a), "=r"(b) : "l"(v));
    lo = __uint_as_float(a); hi = __uint_as_float(b);
}

// ------------------------- generic N=64 GEMM -------------------------
// C[NR,64] = post( A[NR,K] @ B[K,64] )    (A row stride == K, B row stride == 64)
// DUAL: A = w0*A0 + w1*A1 (adjacency conv fuse); COLS: += cb*colsum[col]
// SPIKE: apply spike; ADDX: += X; C2W: also write C2.
struct KA {
    const float* A0;
    const float* A1;
    const float* B;
    const float* X;
    float* C;
    float* C2;
    const float* cs;   // colsum [64]
    const float* cw;   // conv weights [2]
    const float* cb;   // conv bias [1]
    int K;
};

template<bool DUAL, bool SPIKE, bool ADDX, bool COLS, bool C2W>
__global__ void __launch_bounds__(128) gemm_n64(KA a0, KA a1){
    const KA a = blockIdx.y ? a1 : a0;
    const int tid = threadIdx.x;
    const int tx = tid & 7;       // rows 4*tx .. 4*tx+3   (32 rows)
    const int ty = tid >> 3;      // cols 4*ty .. 4*ty+3   (64 cols)
    const int row0 = blockIdx.x * 32;
    const int K = a.K;
    const int nt = K >> 3;

    __shared__ float As[8][36];   // [k][row], pad 36 -> conflict-free, 16B aligned rows
    __shared__ ull   Bs[8][32];   // [k][colpair]

    const int lrow = tid >> 2;          // 0..31
    const int lk2  = (tid & 3) * 2;     // 0,2,4,6
    const int bk   = tid >> 4;          // 0..7
    const int bc4  = (tid & 15) * 4;    // 0..60

    const float* Aptr0 = a.A0 + (size_t)(row0 + lrow) * K + lk2;
    const float* Aptr1 = DUAL ? (a.A1 + (size_t)(row0 + lrow) * K + lk2) : (const float*)0;
    const float* Bptr  = a.B + (size_t)bk * 64 + bc4;

    float w0 = 1.0f, w1 = 0.0f;
    if (DUAL){ w0 = a.cw[0]; w1 = a.cw[1]; }

    float2 pa, pa1; float4 pb;
    pa = *(const float2*)(Aptr0);
    if (DUAL) pa1 = *(const float2*)(Aptr1);
    pb = *(const float4*)(Bptr);

    ull acc[4][2];
    #pragma unroll
    for (int i = 0; i < 4; i++){ acc[i][0] = 0ull; acc[i][1] = 0ull; }

    for (int t = 0; t < nt; t++){
        float ax = pa.x, ay = pa.y;
        if (DUAL){ ax = w0*ax + w1*pa1.x; ay = w0*ay + w1*pa1.y; }
        As[lk2][lrow]   = ax;
        As[lk2+1][lrow] = ay;
        Bs[bk][(bc4>>1)]     = pack2(pb.x, pb.y);
        Bs[bk][(bc4>>1) + 1] = pack2(pb.z, pb.w);
        __syncthreads();
        if (t + 1 < nt){
            pa = *(const float2*)(Aptr0 + (size_t)(t+1)*8);
            if (DUAL) pa1 = *(const float2*)(Aptr1 + (size_t)(t+1)*8);
            pb = *(const float4*)(Bptr + (size_t)(t+1)*8*64);
        }
        #pragma unroll
        for (int k = 0; k < 8; k++){
            float4 av = *(const float4*)&As[k][tx*4];
            ull b0 = Bs[k][ty*2], b1 = Bs[k][ty*2+1];
            ull a0 = dup2(av.x), a1r = dup2(av.y), a2 = dup2(av.z), a3 = dup2(av.w);
            ffma2(acc[0][0], a0, b0);  ffma2(acc[0][1], a0, b1);
            ffma2(acc[1][0], a1r, b0); ffma2(acc[1][1], a1r, b1);
            ffma2(acc[2][0], a2, b0);  ffma2(acc[2][1], a2, b1);
            ffma2(acc[3][0], a3, b0);  ffma2(acc[3][1], a3, b1);
        }
        __syncthreads();
    }

    const int col = ty * 4;
    float cs0 = 0.f, cs1 = 0.f, cs2 = 0.f, cs3 = 0.f;
    if (COLS){
        float cb = a.cb[0];
        cs0 = cb * a.cs[col];   cs1 = cb * a.cs[col+1];
        cs2 = cb * a.cs[col+2]; cs3 = cb * a.cs[col+3];
    }
    #pragma unroll
    for (int i = 0; i < 4; i++){
        int r = row0 + tx*4 + i;
        float v0, v1, v2, v3;
        unpack2(acc[i][0], v0, v1);
        unpack2(acc[i][1], v2, v3);
        if (COLS){ v0 += cs0; v1 += cs1; v2 += cs2; v3 += cs3; }
        if (ADDX){
            const float* xr = a.X + (size_t)r*64 + col;
            v0 += xr[0]; v1 += xr[1]; v2 += xr[2]; v3 += xr[3];
        }
        if (SPIKE){ v0 = spikef(v0); v1 = spikef(v1); v2 = spikef(v2); v3 = spikef(v3); }
        float* cp = a.C + (size_t)r*64 + col;
        *(float2*)cp       = make_float2(v0, v1);
        *(float2*)(cp + 2) = make_float2(v2, v3);
        if (C2W){
            float* c2 = a.C2 + (size_t)r*64 + col;
            *(float2*)c2       = make_float2(v0, v1);
            *(float2*)(c2 + 2) = make_float2(v2, v3);
        }
    }
}

// ------------------------- column sums of fe -------------------------
__global__ void __launch_bounds__(256) colsum_kernel(){
    int c = blockIdx.x, om = blockIdx.y;
    float s = 0.f;
    for (int r = threadIdx.x; r < NR; r += 256) s += g_fe[om][(size_t)r*64 + c];
    __shared__ float red[256];
    red[threadIdx.x] = s;
    __syncthreads();
    for (int o = 128; o > 0; o >>= 1){
        if (threadIdx.x < o) red[threadIdx.x] += red[threadIdx.x + o];
        __syncthreads();
    }
    if (threadIdx.x == 0) g_cs[om][c] = red[0];
}

// ------------------------- partial kv = sum_n k[n,h,d] v[n,h,e] -------------------------
__global__ void __launch_bounds__(512) kvpart_kernel(){
    int om = blockIdx.y, bx = blockIdx.x;
    int tid = threadIdx.x;
    int h = tid >> 6, d = (tid >> 3) & 7, e = tid & 7;
    __shared__ float ks[8][64], vs[8][64];
    int r0 = bx * 128;
    int lr = tid >> 6, lc = tid & 63;
    float acc = 0.f;
    for (int c = 0; c < 16; c++){
        ks[lr][lc] = g_k[om][(size_t)(r0 + c*8 + lr)*64 + lc];
        vs[lr][lc] = g_v[om][(size_t)(r0 + c*8 + lr)*64 + lc];
        __syncthreads();
        #pragma unroll
        for (int n = 0; n < 8; n++)
            acc += ks[n][h*8 + d] * vs[n][h*8 + e];
        __syncthreads();
    }
    g_kvp[om][bx][tid] = acc;
}

// ------------------------- reduce kv, build M[hd,c] = 0.25 * sum_e kv[h,d,e] wp[he,c] ------
__global__ void __launch_bounds__(512) kvm_kernel(const float* wp0, const float* wp1){
    int om = blockIdx.x;
    const float* wp = om ? wp1 : wp0;
    int tid = threadIdx.x;
    __shared__ float kvs[512];
    float s = 0.f;
    for (int b = 0; b < 48; b++) s += g_kvp[om][b][tid];
    kvs[tid] = s;
    __syncthreads();
    #pragma unroll
    for (int i = 0; i < 8; i++){
        int idx = tid + i*512;
        int hd = idx >> 6, c = idx & 63;
        int h = hd >> 3, dd = hd & 7;
        float m = 0.f;
        #pragma unroll
        for (int e = 0; e < 8; e++)
            m += kvs[h*64 + dd*8 + e] * wp[(h*8 + e)*64 + c];
        g_M[om][idx] = 0.25f * m;
    }
}

// ------------------------- fused MLP: comb = spike(cat@fc1+b1)@fc2+b2, out3=spike(comb) ----
__global__ void __launch_bounds__(256) fc_kernel(const float* fc1w, const float* fc1b,
                                                 const float* fc2w, const float* fc2b,
                                                 float* out3){
    __shared__ float cat_s[64][129];   // [row][k], reused for h in phase 2
    int tid = threadIdx.x;
    int row0 = blockIdx.x * 64;
    int tx = tid & 15, ty = tid >> 4;

    for (int i = tid; i < 64*128; i += 256){
        int row = i >> 7, k = i & 127;
        float v = (k < 64) ? g_emb[0][(size_t)(row0+row)*64 + k]
                           : g_emb[1][(size_t)(row0+row)*64 + (k - 64)];
        cat_s[row][k] = v;
    }
    __syncthreads();

    float acc[4][4];
    #pragma unroll
    for (int i = 0; i < 4; i++)
        #pragma unroll
        for (int j = 0; j < 4; j++) acc[i][j] = 0.f;

    for (int k = 0; k < 128; k++){
        float aa[4], bb[4];
        #pragma unroll
        for (int i = 0; i < 4; i++) aa[i] = cat_s[tx*4 + i][k];
        #pragma unroll
        for (int j = 0; j < 4; j++) bb[j] = fc1w[k*64 + ty*4 + j];
        #pragma unroll
        for (int i = 0; i < 4; i++)
            #pragma unroll
            for (int j = 0; j < 4; j++) acc[i][j] += aa[i]*bb[j];
    }
    __syncthreads();   // everyone done reading cat before overwrite
    #pragma unroll
    for (int i = 0; i < 4; i++)
        #pragma unroll
        for (int j = 0; j < 4; j++)
            cat_s[tx*4 + i][ty*4 + j] = spikef(acc[i][j] + fc1b[ty*4 + j]);
    __syncthreads();

    float acc2[4][4];
    #pragma unroll
    for (int i = 0; i < 4; i++)
        #pragma unroll
        for (int j = 0; j < 4; j++) acc2[i][j] = 0.f;
    for (int k = 0; k < 64; k++){
        float aa[4], bb[4];
        #pragma unroll
        for (int i = 0; i < 4; i++) aa[i] = cat_s[tx*4 + i][k];
        #pragma unroll
        for (int j = 0; j < 4; j++) bb[j] = fc2w[k*64 + ty*4 + j];
        #pragma unroll
        for (int i = 0; i < 4; i++)
            #pragma unroll
            for (int j = 0; j < 4; j++) acc2[i][j] += aa[i]*bb[j];
    }
    #pragma unroll
    for (int i = 0; i < 4; i++)
        #pragma unroll
        for (int j = 0; j < 4; j++){
            int r = row0 + tx*4 + i, c = ty*4 + j;
            float v = acc2[i][j] + fc2b[c];
            g_comb[(size_t)r*64 + c] = v;
            out3[(size_t)r*64 + c]   = spikef(v);
        }
}

// ------------------------- recon: C[NR,DN] = spike(U[NR,64] @ W[64,DN]) -------------------
__global__ void __launch_bounds__(128) recon_kernel(const float* U, const float* W,
                                                    int DN, float* out){
    int tid = threadIdx.x;
    int tx = tid & 7, ty = tid >> 3;
    int row0 = blockIdx.x * 32;
    int n0 = blockIdx.y * 64;

    __shared__ float As[8][36];
    __shared__ ull   Bs[8][32];

    int lrow = tid >> 2, lk2 = (tid & 3) * 2;
    int bk = tid >> 4, bc4 = (tid & 15) * 4;

    ull acc[4][2];
    #pragma unroll
    for (int i = 0; i < 4; i++){ acc[i][0] = 0ull; acc[i][1] = 0ull; }

    for (int t = 0; t < 8; t++){
        int k0 = t * 8;
        float2 av = *(const float2*)(U + (size_t)(row0 + lrow)*64 + k0 + lk2);
        As[lk2][lrow]   = av.x;
        As[lk2+1][lrow] = av.y;
        float4 bv = make_float4(0.f, 0.f, 0.f, 0.f);
        if (n0 + bc4 + 4 <= DN)
            bv = *(const float4*)(W + (size_t)(k0 + bk)*DN + n0 + bc4);
        Bs[bk][(bc4>>1)]     = pack2(bv.x, bv.y);
        Bs[bk][(bc4>>1) + 1] = pack2(bv.z, bv.w);
        __syncthreads();
        #pragma unroll
        for (int k = 0; k < 8; k++){
            float4 a4 = *(const float4*)&As[k][tx*4];
            ull b0 = Bs[k][ty*2], b1 = Bs[k][ty*2+1];
            ull a0 = dup2(a4.x), a1r = dup2(a4.y), a2 = dup2(a4.z), a3 = dup2(a4.w);
            ffma2(acc[0][0], a0, b0);  ffma2(acc[0][1], a0, b1);
            ffma2(acc[1][0], a1r, b0); ffma2(acc[1][1], a1r, b1);
            ffma2(acc[2][0], a2, b0);  ffma2(acc[2][1], a2, b1);
            ffma2(acc[3][0], a3, b0);  ffma2(acc[3][1], a3, b1);
        }
        __syncthreads();
    }

    #pragma unroll
    for (int i = 0; i < 4; i++){
        int r = row0 + tx*4 + i;
        float v0, v1, v2, v3;
        unpack2(acc[i][0], v0, v1);
        unpack2(acc[i][1], v2, v3);
        int c0 = n0 + ty*4;
        if (c0 < DN)     *(float2*)(out + (size_t)r*DN + c0)     = make_float2(spikef(v0), spikef(v1));
        if (c0 + 2 < DN) *(float2*)(out + (size_t)r*DN + c0 + 2) = make_float2(spikef(v2), spikef(v3));
    }
}

// ------------------------- launch -------------------------
extern "C" void kernel_launch(void* const* d_in, const int* in_sizes, int n_in,
                              void* d_out, int out_size){
    const float* feat1 = (const float*)d_in[0];
    const float* feat2 = (const float*)d_in[1];
    const float* AS1   = (const float*)d_in[2];
    const float* AF1   = (const float*)d_in[3];
    const float* AS2   = (const float*)d_in[4];
    const float* AF2   = (const float*)d_in[5];
    const float* c1w   = (const float*)d_in[6];
    const float* c1b   = (const float*)d_in[7];
    const float* c2w   = (const float*)d_in[8];
    const float* c2b   = (const float*)d_in[9];
    const float* wenc1 = (const float*)d_in[10];
    const float* wq1   = (const float*)d_in[11];
    const float* wk1   = (const float*)d_in[12];
    const float* wv1   = (const float*)d_in[13];
    const float* wp1   = (const float*)d_in[14];
    const float* wenc2 = (const float*)d_in[15];
    const float* wq2   = (const float*)d_in[16];
    const float* wk2   = (const float*)d_in[17];
    const float* wv2   = (const float*)d_in[18];
    const float* wp2   = (const float*)d_in[19];
    const float* fc1w  = (const float*)d_in[20];
    const float* fc1b  = (const float*)d_in[21];
    const float* fc2w  = (const float*)d_in[22];
    const float* fc2b  = (const float*)d_in[23];
    const float* wdec1 = (const float*)d_in[24];
    const float* wdec2 = (const float*)d_in[25];
    float* out = (float*)d_out;

    float *p_fe, *p_cs, *p_x, *p_q, *p_k, *p_v, *p_M, *p_emb, *p_comb, *p_u;
    cudaGetSymbolAddress((void**)&p_fe,  g_fe);
    cudaGetSymbolAddress((void**)&p_cs,  g_cs);
    cudaGetSymbolAddress((void**)&p_x,   g_x);
    cudaGetSymbolAddress((void**)&p_q,   g_q);
    cudaGetSymbolAddress((void**)&p_k,   g_k);
    cudaGetSymbolAddress((void**)&p_v,   g_v);
    cudaGetSymbolAddress((void**)&p_M,   g_M);
    cudaGetSymbolAddress((void**)&p_emb, g_emb);
    cudaGetSymbolAddress((void**)&p_comb,g_comb);
    cudaGetSymbolAddress((void**)&p_u,   g_u);
    const int OFF = NR*64;

    dim3 g192(192, 2);

    // 1. fe = feat @ w_enc
    {
        KA a0{feat1, nullptr, wenc1, nullptr, p_fe,        nullptr, nullptr, nullptr, nullptr, 3000};
        KA a1{feat2, nullptr, wenc2, nullptr, p_fe + OFF,  nullptr, nullptr, nullptr, nullptr, 512};
        gemm_n64<false,false,false,false,false><<<g192, 128>>>(a0, a1);
    }
    // 2. column sums of fe
    colsum_kernel<<<dim3(64, 2), 256>>>();
    // 3. x = spike((w0*AS + w1*AF) @ fe + cb*colsum)
    {
        KA a0{AS1, AF1, p_fe,       nullptr, p_x,       nullptr, p_cs,      c1w, c1b, NR};
        KA a1{AS2, AF2, p_fe + OFF, nullptr, p_x + OFF, nullptr, p_cs + 64, c2w, c2b, NR};
        gemm_n64<true,true,false,true,false><<<g192, 128>>>(a0, a1);
    }
    // 4. q, k, v = spike(x @ w)
    {
        KA a0{p_x, nullptr, wq1, nullptr, p_q,       nullptr, nullptr, nullptr, nullptr, 64};
        KA a1{p_x + OFF, nullptr, wq2, nullptr, p_q + OFF, nullptr, nullptr, nullptr, nullptr, 64};
        gemm_n64<false,true,false,false,false><<<g192, 128>>>(a0, a1);
    }
    {
        KA a0{p_x, nullptr, wk1, nullptr, p_k,       nullptr, nullptr, nullptr, nullptr, 64};
        KA a1{p_x + OFF, nullptr, wk2, nullptr, p_k + OFF, nullptr, nullptr, nullptr, nullptr, 64};
        gemm_n64<false,true,false,false,false><<<g192, 128>>>(a0, a1);
    }
    {
        KA a0{p_x, nullptr, wv1, nullptr, p_v,       nullptr, nullptr, nullptr, nullptr, 64};
        KA a1{p_x + OFF, nullptr, wv2, nullptr, p_v + OFF, nullptr, nullptr, nullptr, nullptr, 64};
        gemm_n64<false,true,false,false,false><<<g192, 128>>>(a0, a1);
    }
    // 5-6. kv partials, reduce + fold wp into M
    kvpart_kernel<<<dim3(48, 2), 512>>>();
    kvm_kernel<<<2, 512>>>(wp1, wp2);
    // 7. emb = x + q @ M   (also writes emb1/emb2 output regions)
    {
        KA a0{p_q, nullptr, p_M, p_x, p_emb, out, nullptr, nullptr, nullptr, 64};
        KA a1{p_q + OFF, nullptr, p_M + 4096, p_x + OFF, p_emb + OFF, out + OFF,
              nullptr, nullptr, nullptr, 64};
        gemm_n64<false,false,true,false,true><<<g192, 128>>>(a0, a1);
    }
    // 8. MLP: comb (+ out3 = spike(comb))
    fc_kernel<<<96, 256>>>(fc1w, fc1b, fc2w, fc2b, out + 2*OFF);
    // 9. u = AS @ comb
    {
        KA a0{AS1, nullptr, p_comb, nullptr, p_u,       nullptr, nullptr, nullptr, nullptr, NR};
        KA a1{AS2, nullptr, p_comb, nullptr, p_u + OFF, nullptr, nullptr, nullptr, nullptr, NR};
        gemm_n64<false,false,false,false,false><<<g192, 128>>>(a0, a1);
    }
    // 10. recon = spike(u @ w_dec)
    recon_kernel<<<dim3(192, 47), 128>>>(p_u, wdec1, 3000, out + 3*OFF);
    recon_kernel<<<dim3(192, 8),  128>>>(p_u + OFF, wdec2, 512, out + 3*OFF + (size_t)NR*3000);
}